// round 17
// baseline (speedup 1.0000x reference)
#include <cuda_runtime.h>
#include <cuda_fp16.h>
#include <cstdint>

#define BATCH 32
#define CIN 128
#define OUTC 128
#define HIDDEN 32
#define TEMP 31.0f
#define HW 3136
#define PIXB 128
#define NPB 25
#define NPBLK 49

// conv dynamic smem: bias @0, A halo (348 rows * 128B) @1024, B ring 4x16KB
#define SM_A 1024
#define A_ROWS 348
#define A_BYTES (A_ROWS * 128)       // 44544
#define SM_B (SM_A + A_BYTES)        // 45568
#define SM_TOT (SM_B + 4 * 16384)    // 111104 -> 2 CTAs/SM

__device__ float g_attn[BATCH][2];
__device__ float g_part[BATCH * NPBLK * CIN];   // [b][blk][c]
__device__ int   g_cnt[BATCH];                  // zero-init; self-resetting
__device__ __align__(16) __half g_xh[(size_t)BATCH * HW * CIN];          // NHWC
__device__ __align__(16) __half g_wagg[(size_t)BATCH * 9 * OUTC * CIN];  // [b][t][o][c]

#define SWZ(o) ((o) ^ (((o) >> 3) & 0x70))

__device__ __forceinline__ uint32_t smem_u32(const void* p) {
    uint32_t a;
    asm("{ .reg .u64 t; cvta.to.shared.u64 t, %1; cvt.u32.u64 %0, t; }" : "=r"(a) : "l"(p));
    return a;
}
__device__ __forceinline__ void ldm4(uint32_t* r, uint32_t addr) {
    asm volatile("ldmatrix.sync.aligned.m8n8.x4.shared.b16 {%0,%1,%2,%3}, [%4];"
                 : "=r"(r[0]), "=r"(r[1]), "=r"(r[2]), "=r"(r[3]) : "r"(addr));
}
__device__ __forceinline__ void mma16816(float* c, const uint32_t* a, const uint32_t* b) {
    asm volatile("mma.sync.aligned.m16n8k16.row.col.f32.f16.f16.f32 "
                 "{%0,%1,%2,%3}, {%4,%5,%6,%7}, {%8,%9}, {%0,%1,%2,%3};"
                 : "+f"(c[0]), "+f"(c[1]), "+f"(c[2]), "+f"(c[3])
                 : "r"(a[0]), "r"(a[1]), "r"(a[2]), "r"(a[3]), "r"(b[0]), "r"(b[1]));
}
__device__ __forceinline__ void cpasync16(uint32_t dst, const void* src, uint32_t srcsz) {
    asm volatile("cp.async.cg.shared.global [%0], [%1], 16, %2;"
                 :: "r"(dst), "l"(src), "r"(srcsz) : "memory");
}
#define CP_COMMIT() asm volatile("cp.async.commit_group;" ::: "memory")
#define CP_WAIT0()  asm volatile("cp.async.wait_group 0;" ::: "memory")

// ---- prolog 1: transpose + pooling + FUSED attention MLP (last block per b) ----
// grid (49, 2, 32), block 256.
__global__ void __launch_bounds__(256)
convx_kernel(const float* __restrict__ x, const float* __restrict__ fc1_w,
             const float* __restrict__ fc2_w) {
    __shared__ float t[64][65];
    __shared__ float pooled[CIN], hid[HIDDEN], logits[2];
    __shared__ int is_last;
    const int b = blockIdx.z, c0 = blockIdx.y * 64, p0 = blockIdx.x * 64;
    const int tid = threadIdx.x;

    // load 64 rows x 16 float4 (4 per thread); pool each row in registers
    #pragma unroll
    for (int i = 0; i < 4; ++i) {
        int e = tid + i * 256;
        int row = e >> 4, j = e & 15;
        float4 v = *(const float4*)(x + ((size_t)b * CIN + c0 + row) * HW + p0 + 4 * j);
        t[row][4 * j + 0] = v.x; t[row][4 * j + 1] = v.y;
        t[row][4 * j + 2] = v.z; t[row][4 * j + 3] = v.w;
        float ps = v.x + v.y + v.z + v.w;
        #pragma unroll
        for (int o = 1; o < 16; o <<= 1) ps += __shfl_xor_sync(0xffffffffu, ps, o);
        if ((tid & 15) == 0)
            g_part[((size_t)b * NPBLK + blockIdx.x) * CIN + c0 + row] = ps;
    }
    __syncthreads();

    // store NHWC half2 (proven pattern)
    const int tx = tid & 31, tyy = tid >> 5;
    __half2* xh2 = (__half2*)g_xh;
    #pragma unroll
    for (int g = 0; g < 2; ++g) {
        #pragma unroll
        for (int kk = 0; kk < 4; ++kk) {
            int p = g * 32 + tyy + 8 * kk;
            xh2[((size_t)b * HW + p0 + p) * 64 + (c0 >> 1) + tx] =
                __floats2half2_rn(t[2 * tx][p], t[2 * tx + 1][p]);
        }
    }

    // fused MLP: last arriving block of this batch computes attention
    __threadfence();
    __syncthreads();
    if (tid == 0) {
        int old = atomicAdd(&g_cnt[b], 1);
        is_last = (old == 2 * NPBLK - 1);
    }
    __syncthreads();
    if (!is_last) return;
    __threadfence();                      // acquire all blocks' g_part writes

    if (tid < CIN) {
        const float* pp = g_part + (size_t)b * NPBLK * CIN + tid;
        float s = 0.f;
        #pragma unroll 7
        for (int i = 0; i < NPBLK; ++i) s += pp[i * CIN];
        pooled[tid] = s * (1.0f / (float)HW);
    }
    __syncthreads();
    if (tid < HIDDEN) {
        float h = 0.f;
        for (int c = 0; c < CIN; ++c) h += pooled[c] * fc1_w[tid * CIN + c];
        hid[tid] = fmaxf(h, 0.f);
    }
    __syncthreads();
    if (tid < 2) {
        float l = 0.f;
        for (int j = 0; j < HIDDEN; ++j) l += hid[j] * fc2_w[tid * HIDDEN + j];
        logits[tid] = l;
    }
    __syncthreads();
    if (tid == 0) {
        float l0 = logits[0] / TEMP, l1 = logits[1] / TEMP;
        float m = fmaxf(l0, l1), e0 = __expf(l0 - m), e1 = __expf(l1 - m);
        float inv = 1.0f / (e0 + e1);
        g_attn[b][0] = e0 * inv;
        g_attn[b][1] = e1 * inv;
        g_cnt[b] = 0;                     // reset for next graph replay
    }
}

// ---- prolog 2: weight aggregation -> fp16 [b][t][o][c], 512 CTAs ----
__global__ void aggw_kernel(const float* __restrict__ cw, const float* __restrict__ dw) {
    __shared__ float cs[1152], ds[1152];
    const int o = blockIdx.x, tid = threadIdx.x;
    for (int e = tid; e < 1152; e += 256) {
        cs[e] = cw[(size_t)o * 1152 + e];
        ds[e] = dw[(size_t)o * 1152 + e];
    }
    __syncthreads();
    const int c2 = tid & 63, q = tid >> 6;
    const int bt0 = blockIdx.y * 72 + q * 18;
    __half2* wg2 = (__half2*)g_wagg;
    for (int bt = bt0; bt < bt0 + 18; ++bt) {
        int b = bt / 9, t = bt - b * 9;
        float a0 = g_attn[b][0], a1 = g_attn[b][1];
        float v0 = a0 * cs[(2 * c2) * 9 + t] + a1 * ds[(2 * c2) * 9 + t];
        float v1 = a0 * cs[(2 * c2 + 1) * 9 + t] + a1 * ds[(2 * c2 + 1) * 9 + t];
        wg2[(((size_t)b * 9 + t) * OUTC + o) * 64 + c2] = __floats2half2_rn(v0, v1);
    }
}

// ---- main conv (R16-proven, unchanged): HMMA implicit GEMM, 4-buffer B ring ----
__global__ void __launch_bounds__(256, 2)
conv_kernel(const float* __restrict__ cb, const float* __restrict__ db,
            float* __restrict__ out) {
    extern __shared__ char sm[];
    const uint32_t smb = smem_u32(sm);
    const int tid = threadIdx.x, wid = tid >> 5, lane = tid & 31;
    const int wm = wid & 3, wn = wid >> 2;
    const int b = blockIdx.y, pbase = blockIdx.x * PIXB;
    const int h0 = pbase / 56;

    float* bias = (float*)sm;
    if (tid < OUTC) bias[tid] = g_attn[b][0] * cb[tid] + g_attn[b][1] * db[tid];

    const __half* xb = g_xh + (size_t)b * HW * CIN;
    const __half* wb = g_wagg + (size_t)b * 9 * OUTC * CIN;

    int hh[2], ww[2];
    #pragma unroll
    for (int mi = 0; mi < 2; ++mi) {
        int p = pbase + wm * 32 + mi * 16 + (lane & 15);
        if (p >= HW) p = HW - 1;
        hh[mi] = p / 56;
        ww[mi] = p - hh[mi] * 56;
    }

    float acc[2][8][4];
    #pragma unroll
    for (int mi = 0; mi < 2; ++mi)
        #pragma unroll
        for (int ni = 0; ni < 8; ++ni)
            #pragma unroll
            for (int e = 0; e < 4; ++e) acc[mi][ni][e] = 0.f;

    uint32_t brow[4];
    #pragma unroll
    for (int nb = 0; nb < 4; ++nb)
        brow[nb] = (uint32_t)(wn * 64 + nb * 16 + (lane & 15)) * 128;
    const uint32_t bxr = (uint32_t)(lane & 7) << 4;
    const uint32_t ksub = (uint32_t)((lane >> 4) << 4);

    uint32_t bdst[4];
    int boff[4];
    #pragma unroll
    for (int i = 0; i < 4; ++i) {
        int e = tid + i * 256, o = e >> 3, ch = e & 7;
        bdst[i] = SWZ((uint32_t)o * 128 + ch * 16);
        boff[i] = o * CIN + ch * 8;
    }

    auto stageA = [&](int cofs) {
        #pragma unroll
        for (int ir = 0; ir < 6; ++ir) {
            const int ih = h0 - 1 + ir;
            const bool rok = ((unsigned)ih < 56u);
            #pragma unroll
            for (int i = 0; i < 2; ++i) {
                int e = tid + i * 256;
                if (e < 464) {
                    int col = e >> 3, ch = e & 7;
                    int rr = ir * 58 + col;
                    bool ok = rok && col >= 1 && col <= 56;
                    const void* src = xb + (ok ? ((size_t)(ih * 56 + col - 1) * CIN + cofs + ch * 8) : 0);
                    cpasync16(smb + SM_A + SWZ((uint32_t)rr * 128 + ch * 16), src, ok ? 16u : 0u);
                }
            }
        }
    };

    auto compute = [&](int s) {
        const int hf = s / 9, t = s - hf * 9;
        (void)hf;
        const int di = t / 3, dj = t - di * 3;
        uint32_t abase[2], axr[2];
        #pragma unroll
        for (int mi = 0; mi < 2; ++mi) {
            uint32_t rr = (uint32_t)((hh[mi] - h0 + di) * 58 + ww[mi] + dj);
            abase[mi] = smb + SM_A + rr * 128;
            axr[mi] = (rr & 7) << 4;
        }
        const uint32_t bbuf = smb + SM_B + (uint32_t)((s & 3) * 16384);
        #pragma unroll
        for (int ks = 0; ks < 4; ++ks) {
            const uint32_t kb = (uint32_t)ks * 32 + ksub;
            uint32_t a[2][4], bf[8][2];
            #pragma unroll
            for (int mi = 0; mi < 2; ++mi)
                ldm4(a[mi], abase[mi] + (kb ^ axr[mi]));
            #pragma unroll
            for (int nb = 0; nb < 4; ++nb) {
                uint32_t r[4];
                ldm4(r, bbuf + brow[nb] + (kb ^ bxr));
                bf[nb * 2][0] = r[0]; bf[nb * 2][1] = r[2];
                bf[nb * 2 + 1][0] = r[1]; bf[nb * 2 + 1][1] = r[3];
            }
            #pragma unroll
            for (int mi = 0; mi < 2; ++mi)
                #pragma unroll
                for (int ni = 0; ni < 8; ++ni)
                    mma16816(acc[mi][ni], a[mi], bf[ni]);
        }
    };

    stageA(0);
    #pragma unroll
    for (int j = 0; j < 2; ++j) {
        const __half* src = wb + (size_t)j * OUTC * CIN;
        uint32_t buf = smb + SM_B + (uint32_t)(j * 16384);
        #pragma unroll
        for (int i = 0; i < 4; ++i)
            cpasync16(buf + bdst[i], src + boff[i], 16u);
    }
    CP_COMMIT();
    CP_WAIT0();
    __syncthreads();

    for (int p = 0; p < 9; ++p) {
        if (p < 8) {
            #pragma unroll
            for (int j = 0; j < 2; ++j) {
                const int sn = 2 * p + 2 + j;
                const int hfn = sn / 9, tn = sn - hfn * 9;
                const __half* src = wb + (size_t)tn * OUTC * CIN + hfn * 64;
                uint32_t buf = smb + SM_B + (uint32_t)((sn & 3) * 16384);
                #pragma unroll
                for (int i = 0; i < 4; ++i)
                    cpasync16(buf + bdst[i], src + boff[i], 16u);
            }
            CP_COMMIT();
        }

        compute(2 * p);

        if (p == 4) {
            __syncthreads();
            stageA(64);
            CP_COMMIT();
            CP_WAIT0();
            __syncthreads();
        }

        compute(2 * p + 1);

        if (p < 8) {
            CP_WAIT0();
            __syncthreads();
        }
    }

    float* csm = (float*)(sm + SM_A);
    float* ob = out + (size_t)b * OUTC * HW;
    __syncthreads();
    #pragma unroll
    for (int mi = 0; mi < 2; ++mi) {
        const int prl = wm * 32 + mi * 16 + (lane >> 2);
        #pragma unroll
        for (int ni = 0; ni < 8; ++ni) {
            const int ocl = wn * 64 + ni * 8 + (lane & 3) * 2;
            csm[ocl * 132 + prl]           = acc[mi][ni][0];
            csm[(ocl + 1) * 132 + prl]     = acc[mi][ni][1];
            csm[ocl * 132 + prl + 8]       = acc[mi][ni][2];
            csm[(ocl + 1) * 132 + prl + 8] = acc[mi][ni][3];
        }
    }
    __syncthreads();
    #pragma unroll
    for (int i = 0; i < 16; ++i) {
        int idx = tid + i * 256;
        int ocl = idx >> 5, px4 = idx & 31;
        int pix = pbase + px4 * 4;
        if (pix < HW) {
            float4 v = *(float4*)&csm[ocl * 132 + px4 * 4];
            float bb = bias[ocl];
            v.x += bb; v.y += bb; v.z += bb; v.w += bb;
            *(float4*)&ob[(size_t)ocl * HW + pix] = v;
        }
    }
}

extern "C" void kernel_launch(void* const* d_in, const int* in_sizes, int n_in,
                              void* d_out, int out_size) {
    const float* x     = (const float*)d_in[0];
    const float* cw    = (const float*)d_in[1];
    const float* cb    = (const float*)d_in[2];
    const float* dw    = (const float*)d_in[3];
    const float* db    = (const float*)d_in[4];
    const float* fc1_w = (const float*)d_in[5];
    const float* fc2_w = (const float*)d_in[6];
    float* out = (float*)d_out;

    cudaFuncSetAttribute(conv_kernel, cudaFuncAttributeMaxDynamicSharedMemorySize, SM_TOT);

    convx_kernel<<<dim3(NPBLK, 2, BATCH), 256>>>(x, fc1_w, fc2_w);
    aggw_kernel<<<dim3(OUTC, 4), 256>>>(cw, dw);
    conv_kernel<<<dim3(NPB, BATCH), 256, SM_TOT>>>(cb, db, out);
}